// round 13
// baseline (speedup 1.0000x reference)
#include <cuda_runtime.h>
#include <cuda_bf16.h>
#include <cstdint>
#include <math.h>

#define NN 8192
#define HID 64

// ---------------- device scratch (no allocs allowed) ----------------
__device__ __align__(16) __nv_bfloat16 g_z1h[NN * HID];   // normalized proj of x1 (bf16)
__device__ __align__(16) __nv_bfloat16 g_z2h[NN * HID];   // normalized proj of x2 (bf16)
__device__ float g_rowsum[NN];
__device__ float g_colsum[NN];
__device__ float g_num1[NN];
__device__ float g_num2[NN];

// ---------------- PTX helpers (baseline sm_80-class features only) ----------------
__device__ __forceinline__ uint32_t smem_u32(const void* p) {
    uint32_t a;
    asm("{ .reg .u64 t; cvta.to.shared.u64 t, %1; cvt.u32.u64 %0, t; }" : "=r"(a) : "l"(p));
    return a;
}
__device__ __forceinline__ float ex2f(float x) {
    float y; asm("ex2.approx.ftz.f32 %0, %1;" : "=f"(y) : "f"(x)); return y;
}
#define SWZ128(o) ((o) ^ (((o) >> 3) & 0x70))

__device__ __forceinline__ void ldsm_x4(uint32_t* r, uint32_t addr) {
    asm volatile("ldmatrix.sync.aligned.m8n8.x4.shared.b16 {%0,%1,%2,%3}, [%4];"
                 : "=r"(r[0]), "=r"(r[1]), "=r"(r[2]), "=r"(r[3]) : "r"(addr));
}
// D += A(16x16 bf16, row) * B(16x8 bf16, col)   [f32 accum]
__device__ __forceinline__ void mma16816(float* d, const uint32_t* a, const uint32_t* b) {
    asm volatile(
        "mma.sync.aligned.m16n8k16.row.col.f32.bf16.bf16.f32 "
        "{%0,%1,%2,%3}, {%4,%5,%6,%7}, {%8,%9}, {%0,%1,%2,%3};"
        : "+f"(d[0]), "+f"(d[1]), "+f"(d[2]), "+f"(d[3])
        : "r"(a[0]), "r"(a[1]), "r"(a[2]), "r"(a[3]), "r"(b[0]), "r"(b[1]));
}

// ---------------- K1: zero accumulators + projection (split-K ILP) ----------------
__global__ void __launch_bounds__(256, 3) proj_kernel(
    const float* __restrict__ x1, const float* __restrict__ x2,
    const float* __restrict__ W1, const float* __restrict__ b1,
    const float* __restrict__ W2, const float* __restrict__ b2,
    float* __restrict__ out0)
{
    {
        int gid = blockIdx.x * 256 + threadIdx.x;
        if (gid < NN) {
            g_rowsum[gid] = 0.0f; g_colsum[gid] = 0.0f;
            g_num1[gid]   = 0.0f; g_num2[gid]   = 0.0f;
        }
        if (gid == 0) *out0 = 0.0f;
    }

    __shared__ float sW1[64 * 68];
    __shared__ float sW2[64 * 68];
    __shared__ float sX[8][2][64];
    __shared__ float sH[8][2][64];

    int tid = threadIdx.x;
    {
        const float4* W1f = reinterpret_cast<const float4*>(W1);
        const float4* W2f = reinterpret_cast<const float4*>(W2);
        for (int idx = tid; idx < 1024; idx += 256) {
            int r = idx >> 4, c4 = idx & 15;
            *reinterpret_cast<float4*>(sW1 + r * 68 + c4 * 4) = W1f[idx];
            *reinterpret_cast<float4*>(sW2 + r * 68 + c4 * 4) = W2f[idx];
        }
    }
    __syncthreads();

    int w = tid >> 5, lane = tid & 31;
    int c0 = lane, c1 = lane + 32;
    const float4* w1a = reinterpret_cast<const float4*>(sW1 + c0 * 68);
    const float4* w1b = reinterpret_cast<const float4*>(sW1 + c1 * 68);
    const float4* w2a = reinterpret_cast<const float4*>(sW2 + c0 * 68);
    const float4* w2b = reinterpret_cast<const float4*>(sW2 + c1 * 68);
    const float bia0 = b1[c0], bia1 = b1[c1];
    const float bib0 = b2[c0], bib1 = b2[c1];
    const float L2E = 1.4426950409f;

    int slot = blockIdx.x;
    const float* x = (slot < 512) ? x1 : x2;
    __nv_bfloat16* out = (slot < 512) ? g_z1h : g_z2h;
    int rbase = ((slot & 511) * 16) + w * 2;

    sX[w][0][lane]      = x[rbase * 64 + lane];
    sX[w][0][lane + 32] = x[rbase * 64 + lane + 32];
    sX[w][1][lane]      = x[(rbase + 1) * 64 + lane];
    sX[w][1][lane + 32] = x[(rbase + 1) * 64 + lane + 32];
    __syncwarp();

    const float4* xA = reinterpret_cast<const float4*>(&sX[w][0][0]);
    const float4* xB = reinterpret_cast<const float4*>(&sX[w][1][0]);
    float a0Al = bia0, a0Ah = 0.f, a1Al = bia1, a1Ah = 0.f;
    float a0Bl = bia0, a0Bh = 0.f, a1Bl = bia1, a1Bh = 0.f;
#pragma unroll
    for (int kq = 0; kq < 8; kq++) {
        float4 u0 = w1a[kq], v0 = w1b[kq], qa0 = xA[kq], qb0 = xB[kq];
        float4 u1 = w1a[kq + 8], v1 = w1b[kq + 8], qa1 = xA[kq + 8], qb1 = xB[kq + 8];
        a0Al = fmaf(qa0.x, u0.x, a0Al); a0Al = fmaf(qa0.y, u0.y, a0Al);
        a0Al = fmaf(qa0.z, u0.z, a0Al); a0Al = fmaf(qa0.w, u0.w, a0Al);
        a0Ah = fmaf(qa1.x, u1.x, a0Ah); a0Ah = fmaf(qa1.y, u1.y, a0Ah);
        a0Ah = fmaf(qa1.z, u1.z, a0Ah); a0Ah = fmaf(qa1.w, u1.w, a0Ah);
        a1Al = fmaf(qa0.x, v0.x, a1Al); a1Al = fmaf(qa0.y, v0.y, a1Al);
        a1Al = fmaf(qa0.z, v0.z, a1Al); a1Al = fmaf(qa0.w, v0.w, a1Al);
        a1Ah = fmaf(qa1.x, v1.x, a1Ah); a1Ah = fmaf(qa1.y, v1.y, a1Ah);
        a1Ah = fmaf(qa1.z, v1.z, a1Ah); a1Ah = fmaf(qa1.w, v1.w, a1Ah);
        a0Bl = fmaf(qb0.x, u0.x, a0Bl); a0Bl = fmaf(qb0.y, u0.y, a0Bl);
        a0Bl = fmaf(qb0.z, u0.z, a0Bl); a0Bl = fmaf(qb0.w, u0.w, a0Bl);
        a0Bh = fmaf(qb1.x, u1.x, a0Bh); a0Bh = fmaf(qb1.y, u1.y, a0Bh);
        a0Bh = fmaf(qb1.z, u1.z, a0Bh); a0Bh = fmaf(qb1.w, u1.w, a0Bh);
        a1Bl = fmaf(qb0.x, v0.x, a1Bl); a1Bl = fmaf(qb0.y, v0.y, a1Bl);
        a1Bl = fmaf(qb0.z, v0.z, a1Bl); a1Bl = fmaf(qb0.w, v0.w, a1Bl);
        a1Bh = fmaf(qb1.x, v1.x, a1Bh); a1Bh = fmaf(qb1.y, v1.y, a1Bh);
        a1Bh = fmaf(qb1.z, v1.z, a1Bh); a1Bh = fmaf(qb1.w, v1.w, a1Bh);
    }
    float a0A = a0Al + a0Ah, a1A = a1Al + a1Ah;
    float a0B = a0Bl + a0Bh, a1B = a1Bl + a1Bh;
    a0A = (a0A > 0.0f) ? a0A : (ex2f(a0A * L2E) - 1.0f);   // ELU alpha=1
    a1A = (a1A > 0.0f) ? a1A : (ex2f(a1A * L2E) - 1.0f);
    a0B = (a0B > 0.0f) ? a0B : (ex2f(a0B * L2E) - 1.0f);
    a1B = (a1B > 0.0f) ? a1B : (ex2f(a1B * L2E) - 1.0f);
    sH[w][0][c0] = a0A; sH[w][0][c1] = a1A;
    sH[w][1][c0] = a0B; sH[w][1][c1] = a1B;
    __syncwarp();

    const float4* hA = reinterpret_cast<const float4*>(&sH[w][0][0]);
    const float4* hB = reinterpret_cast<const float4*>(&sH[w][1][0]);
    float z0Al = bib0, z0Ah = 0.f, z1Al = bib1, z1Ah = 0.f;
    float z0Bl = bib0, z0Bh = 0.f, z1Bl = bib1, z1Bh = 0.f;
#pragma unroll
    for (int kq = 0; kq < 8; kq++) {
        float4 u0 = w2a[kq], v0 = w2b[kq], qa0 = hA[kq], qb0 = hB[kq];
        float4 u1 = w2a[kq + 8], v1 = w2b[kq + 8], qa1 = hA[kq + 8], qb1 = hB[kq + 8];
        z0Al = fmaf(qa0.x, u0.x, z0Al); z0Al = fmaf(qa0.y, u0.y, z0Al);
        z0Al = fmaf(qa0.z, u0.z, z0Al); z0Al = fmaf(qa0.w, u0.w, z0Al);
        z0Ah = fmaf(qa1.x, u1.x, z0Ah); z0Ah = fmaf(qa1.y, u1.y, z0Ah);
        z0Ah = fmaf(qa1.z, u1.z, z0Ah); z0Ah = fmaf(qa1.w, u1.w, z0Ah);
        z1Al = fmaf(qa0.x, v0.x, z1Al); z1Al = fmaf(qa0.y, v0.y, z1Al);
        z1Al = fmaf(qa0.z, v0.z, z1Al); z1Al = fmaf(qa0.w, v0.w, z1Al);
        z1Ah = fmaf(qa1.x, v1.x, z1Ah); z1Ah = fmaf(qa1.y, v1.y, z1Ah);
        z1Ah = fmaf(qa1.z, v1.z, z1Ah); z1Ah = fmaf(qa1.w, v1.w, z1Ah);
        z0Bl = fmaf(qb0.x, u0.x, z0Bl); z0Bl = fmaf(qb0.y, u0.y, z0Bl);
        z0Bl = fmaf(qb0.z, u0.z, z0Bl); z0Bl = fmaf(qb0.w, u0.w, z0Bl);
        z0Bh = fmaf(qb1.x, u1.x, z0Bh); z0Bh = fmaf(qb1.y, u1.y, z0Bh);
        z0Bh = fmaf(qb1.z, u1.z, z0Bh); z0Bh = fmaf(qb1.w, u1.w, z0Bh);
        z1Bl = fmaf(qb0.x, v0.x, z1Bl); z1Bl = fmaf(qb0.y, v0.y, z1Bl);
        z1Bl = fmaf(qb0.z, v0.z, z1Bl); z1Bl = fmaf(qb0.w, v0.w, z1Bl);
        z1Bh = fmaf(qb1.x, v1.x, z1Bh); z1Bh = fmaf(qb1.y, v1.y, z1Bh);
        z1Bh = fmaf(qb1.z, v1.z, z1Bh); z1Bh = fmaf(qb1.w, v1.w, z1Bh);
    }
    float z0A = z0Al + z0Ah, z1A = z1Al + z1Ah;
    float z0B = z0Bl + z0Bh, z1B = z1Bl + z1Bh;
    float ssA = z0A * z0A + z1A * z1A;
    float ssB = z0B * z0B + z1B * z1B;
#pragma unroll
    for (int o = 16; o > 0; o >>= 1) {
        ssA += __shfl_xor_sync(0xffffffffu, ssA, o);
        ssB += __shfl_xor_sync(0xffffffffu, ssB, o);
    }
    float invA = 1.0f / fmaxf(sqrtf(ssA), 1e-12f);
    float invB = 1.0f / fmaxf(sqrtf(ssB), 1e-12f);
    out[rbase * 64 + c0]       = __float2bfloat16(z0A * invA);
    out[rbase * 64 + c1]       = __float2bfloat16(z1A * invA);
    out[(rbase + 1) * 64 + c0] = __float2bfloat16(z0B * invB);
    out[(rbase + 1) * 64 + c1] = __float2bfloat16(z1B * invB);
}

// ---------------- K2: two thin row-aligned passes per block ----------------
// Pass 1: T1 = z1[bi] @ z2[bj]^T -> rowsum/num1   (pos tile from DRAM)
// Pass 2: T2 = z2[bi] @ z1[bj]^T -> colsum/num2   (same pos tile, L2-resident)
// No shfl chains in the mainloop, no queues, no smem atomics.
#define SMEM_B1P 0                    // z2[bj] tile, 16384 B
#define SMEM_B2P 16384                // z1[bj] tile, 16384 B
#define SMEM_TOT 32768

// One pass: A rows (LDG frags), B tile in smem, pos row-aligned consume.
__device__ __forceinline__ void sim_pass(
    uint32_t smemB, const __nv_bfloat16* __restrict__ Abase,
    const float* __restrict__ posq,   // pos + R0*NN + bj*128 + 2*qc
    float* __restrict__ out_sum, float* __restrict__ out_num,
    int R0, int lane)
{
    int rr = lane & 7, g = lane >> 3;
    int qc = lane & 3;

    // A fragments via direct LDG (m16n8k16 A layout; validated in R12)
    uint32_t a[16];
    {
        const char* ar0 = reinterpret_cast<const char*>(Abase);          // row R0
        const char* ar1 = ar0 + 8 * 128;                                  // row R0+8
#pragma unroll
        for (int s = 0; s < 4; s++) {
            a[4 * s + 0] = *reinterpret_cast<const uint32_t*>(ar0 + s * 32 + 4 * qc);
            a[4 * s + 1] = *reinterpret_cast<const uint32_t*>(ar1 + s * 32 + 4 * qc);
            a[4 * s + 2] = *reinterpret_cast<const uint32_t*>(ar0 + s * 32 + 16 + 4 * qc);
            a[4 * s + 3] = *reinterpret_cast<const uint32_t*>(ar1 + s * 32 + 16 + 4 * qc);
        }
    }

    const float* p0base = posq;
    const float* p1base = posq + (size_t)8 * NN;

    float rs_a = 0.f, rs_b = 0.f, nm_a = 0.f, nm_b = 0.f;
    const float cexp = 1.8033688011f;              // log2(e)/tau

#pragma unroll
    for (int nf = 0; nf < 16; nf++) {
        float2 p0 = *reinterpret_cast<const float2*>(p0base + nf * 8);
        float2 p1 = *reinterpret_cast<const float2*>(p1base + nf * 8);

        uint32_t bb[8];
        int rowB = nf * 8 + rr;
        uint32_t offL = SWZ128((uint32_t)(rowB * 128 + g * 16));
        uint32_t offH = SWZ128((uint32_t)(rowB * 128 + (g + 4) * 16));
        ldsm_x4(bb,     smemB + offL);
        ldsm_x4(bb + 4, smemB + offH);

        float d[4] = {0.f, 0.f, 0.f, 0.f};
#pragma unroll
        for (int s = 0; s < 4; s++) mma16816(d, a + 4 * s, bb + 2 * s);

        float e0 = ex2f(d[0] * cexp), e1 = ex2f(d[1] * cexp);
        float e2 = ex2f(d[2] * cexp), e3 = ex2f(d[3] * cexp);

        rs_a += e0 + e1;  rs_b += e2 + e3;
        nm_a = fmaf(p0.x, e0, nm_a); nm_a = fmaf(p0.y, e1, nm_a);
        nm_b = fmaf(p1.x, e2, nm_b); nm_b = fmaf(p1.y, e3, nm_b);
    }

    // quad reduce (over qc) and 4 atomics from quad leaders
#pragma unroll
    for (int o = 1; o <= 2; o <<= 1) {
        rs_a += __shfl_xor_sync(0xffffffffu, rs_a, o);
        rs_b += __shfl_xor_sync(0xffffffffu, rs_b, o);
        nm_a += __shfl_xor_sync(0xffffffffu, nm_a, o);
        nm_b += __shfl_xor_sync(0xffffffffu, nm_b, o);
    }
    if (qc == 0) {
        atomicAdd(&out_sum[R0],     rs_a);
        atomicAdd(&out_sum[R0 + 8], rs_b);
        atomicAdd(&out_num[R0],     nm_a);
        atomicAdd(&out_num[R0 + 8], nm_b);
    }
}

__global__ void __launch_bounds__(256, 4) sim_mma_kernel(const float* __restrict__ pos)
{
    extern __shared__ char smem[];
    uint32_t sbase = smem_u32(smem);

    int tid = threadIdx.x, w = tid >> 5, lane = tid & 31;
    int bi = blockIdx.y, bj = blockIdx.x;
    int qr = lane >> 2, qc = lane & 3;

    // ---- load both B tiles (SW128-swizzled): z2[bj] and z1[bj]
    {
        const float4* srcB1 = reinterpret_cast<const float4*>(g_z2h) + bj * 1024;
        const float4* srcB2 = reinterpret_cast<const float4*>(g_z1h) + bj * 1024;
        for (int idx = tid; idx < 1024; idx += 256) {
            int rrow = idx >> 3, q = idx & 7;
            uint32_t sw = SWZ128((uint32_t)(rrow * 128 + q * 16));
            *reinterpret_cast<float4*>(smem + SMEM_B1P + sw) = srcB1[idx];
            *reinterpret_cast<float4*>(smem + SMEM_B2P + sw) = srcB2[idx];
        }
    }
    __syncthreads();

    int R0 = bi * 128 + 16 * w + qr;
    const float* posq = pos + (size_t)R0 * NN + bj * 128 + 2 * qc;

    // pass 1: z1[bi] x z2[bj]  -> rowsum / num1
    sim_pass(sbase + SMEM_B1P,
             g_z1h + (size_t)R0 * HID,
             posq, g_rowsum, g_num1, R0, lane);

    // pass 2: z2[bi] x z1[bj]  -> colsum / num2  (pos tile now L2-hot)
    sim_pass(sbase + SMEM_B2P,
             g_z2h + (size_t)R0 * HID,
             posq, g_colsum, g_num2, R0, lane);
}

// ---------------- K3: final loss reduction ----------------
__global__ void __launch_bounds__(256) final_kernel(float* __restrict__ out)
{
    __shared__ float red[8];
    int i = blockIdx.x * 256 + threadIdx.x;
    float rsum = g_rowsum[i] + 1e-8f;
    float csum = g_colsum[i] + 1e-8f;
    float term = -0.5f * (logf(g_num1[i] / rsum + 1e-8f) +
                          logf(g_num2[i] / csum + 1e-8f)) * (1.0f / NN);
#pragma unroll
    for (int o = 16; o > 0; o >>= 1) term += __shfl_xor_sync(0xffffffffu, term, o);
    int w = threadIdx.x >> 5, lane = threadIdx.x & 31;
    if (lane == 0) red[w] = term;
    __syncthreads();
    if (threadIdx.x == 0) {
        float s = 0.0f;
#pragma unroll
        for (int t = 0; t < 8; t++) s += red[t];
        atomicAdd(out, s);
    }
}

// ---------------- host launcher ----------------
extern "C" void kernel_launch(void* const* d_in, const int* in_sizes, int n_in,
                              void* d_out, int out_size)
{
    const float* x1  = (const float*)d_in[0];
    const float* x2  = (const float*)d_in[1];
    const float* W1  = (const float*)d_in[2];
    const float* b1  = (const float*)d_in[3];
    const float* W2  = (const float*)d_in[4];
    const float* b2  = (const float*)d_in[5];
    const float* pos = (const float*)d_in[6];

    proj_kernel<<<1024, 256>>>(x1, x2, W1, b1, W2, b2, (float*)d_out);

    cudaFuncSetAttribute(sim_mma_kernel, cudaFuncAttributeMaxDynamicSharedMemorySize, SMEM_TOT);
    sim_mma_kernel<<<dim3(64, 64), 256, SMEM_TOT>>>(pos);

    final_kernel<<<32, 256>>>((float*)d_out);
}

// round 14
// speedup vs baseline: 1.5098x; 1.5098x over previous
#include <cuda_runtime.h>
#include <cuda_fp16.h>
#include <cstdint>
#include <math.h>

#define NN 8192
#define HID 64

// ---------------- device scratch (no allocs allowed) ----------------
__device__ __align__(16) __half g_z1h[NN * HID];   // normalized proj of x1 (fp16)
__device__ __align__(16) __half g_z2h[NN * HID];   // normalized proj of x2 (fp16)
__device__ float g_rowsum[NN];
__device__ float g_colsum[NN];
__device__ float g_num1[NN];
__device__ float g_num2[NN];

// ---------------- PTX helpers (baseline sm_80-class features only) ----------------
__device__ __forceinline__ uint32_t smem_u32(const void* p) {
    uint32_t a;
    asm("{ .reg .u64 t; cvta.to.shared.u64 t, %1; cvt.u32.u64 %0, t; }" : "=r"(a) : "l"(p));
    return a;
}
__device__ __forceinline__ float ex2f(float x) {
    float y; asm("ex2.approx.ftz.f32 %0, %1;" : "=f"(y) : "f"(x)); return y;
}
#define SWZ128(o) ((o) ^ (((o) >> 3) & 0x70))

__device__ __forceinline__ void ldsm_x4(uint32_t* r, uint32_t addr) {
    asm volatile("ldmatrix.sync.aligned.m8n8.x4.shared.b16 {%0,%1,%2,%3}, [%4];"
                 : "=r"(r[0]), "=r"(r[1]), "=r"(r[2]), "=r"(r[3]) : "r"(addr));
}
// D(f16x4) += A(16x16 f16, row) * B(16x8 f16, col) -- f16 accumulator (2x rate on
// every prior arch's legacy path; the experiment this round tests on sm_103a)
__device__ __forceinline__ void mma16816_f16(uint32_t* d, const uint32_t* a, const uint32_t* b) {
    asm volatile(
        "mma.sync.aligned.m16n8k16.row.col.f16.f16.f16.f16 "
        "{%0,%1}, {%2,%3,%4,%5}, {%6,%7}, {%0,%1};"
        : "+r"(d[0]), "+r"(d[1])
        : "r"(a[0]), "r"(a[1]), "r"(a[2]), "r"(a[3]), "r"(b[0]), "r"(b[1]));
}
__device__ __forceinline__ void cp_async16(uint32_t dst, const void* src) {
    asm volatile("cp.async.cg.shared.global [%0], [%1], 16;"
                 :: "r"(dst), "l"(src) : "memory");
}
__device__ __forceinline__ void cp_commit() {
    asm volatile("cp.async.commit_group;" ::: "memory");
}
__device__ __forceinline__ float h2dot(uint32_t a, uint32_t b, float acc) {
    float2 fa = __half22float2(reinterpret_cast<const __half2&>(a));
    float2 fb = __half22float2(reinterpret_cast<const __half2&>(b));
    acc = fmaf(fa.x, fb.x, acc);
    return fmaf(fa.y, fb.y, acc);
}

// ---------------- K1: zero accumulators + projection (split-K ILP) ----------------
__global__ void __launch_bounds__(256, 3) proj_kernel(
    const float* __restrict__ x1, const float* __restrict__ x2,
    const float* __restrict__ W1, const float* __restrict__ b1,
    const float* __restrict__ W2, const float* __restrict__ b2,
    float* __restrict__ out0)
{
    {
        int gid = blockIdx.x * 256 + threadIdx.x;
        if (gid < NN) {
            g_rowsum[gid] = 0.0f; g_colsum[gid] = 0.0f;
            g_num1[gid]   = 0.0f; g_num2[gid]   = 0.0f;
        }
        if (gid == 0) *out0 = 0.0f;
    }

    __shared__ float sW1[64 * 68];
    __shared__ float sW2[64 * 68];
    __shared__ float sX[8][2][64];
    __shared__ float sH[8][2][64];

    int tid = threadIdx.x;
    {
        const float4* W1f = reinterpret_cast<const float4*>(W1);
        const float4* W2f = reinterpret_cast<const float4*>(W2);
        for (int idx = tid; idx < 1024; idx += 256) {
            int r = idx >> 4, c4 = idx & 15;
            *reinterpret_cast<float4*>(sW1 + r * 68 + c4 * 4) = W1f[idx];
            *reinterpret_cast<float4*>(sW2 + r * 68 + c4 * 4) = W2f[idx];
        }
    }
    __syncthreads();

    int w = tid >> 5, lane = tid & 31;
    int c0 = lane, c1 = lane + 32;
    const float4* w1a = reinterpret_cast<const float4*>(sW1 + c0 * 68);
    const float4* w1b = reinterpret_cast<const float4*>(sW1 + c1 * 68);
    const float4* w2a = reinterpret_cast<const float4*>(sW2 + c0 * 68);
    const float4* w2b = reinterpret_cast<const float4*>(sW2 + c1 * 68);
    const float bia0 = b1[c0], bia1 = b1[c1];
    const float bib0 = b2[c0], bib1 = b2[c1];
    const float L2E = 1.4426950409f;

    int slot = blockIdx.x;
    const float* x = (slot < 512) ? x1 : x2;
    __half* out = (slot < 512) ? g_z1h : g_z2h;
    int rbase = ((slot & 511) * 16) + w * 2;

    sX[w][0][lane]      = x[rbase * 64 + lane];
    sX[w][0][lane + 32] = x[rbase * 64 + lane + 32];
    sX[w][1][lane]      = x[(rbase + 1) * 64 + lane];
    sX[w][1][lane + 32] = x[(rbase + 1) * 64 + lane + 32];
    __syncwarp();

    const float4* xA = reinterpret_cast<const float4*>(&sX[w][0][0]);
    const float4* xB = reinterpret_cast<const float4*>(&sX[w][1][0]);
    float a0Al = bia0, a0Ah = 0.f, a1Al = bia1, a1Ah = 0.f;
    float a0Bl = bia0, a0Bh = 0.f, a1Bl = bia1, a1Bh = 0.f;
#pragma unroll
    for (int kq = 0; kq < 8; kq++) {
        float4 u0 = w1a[kq], v0 = w1b[kq], qa0 = xA[kq], qb0 = xB[kq];
        float4 u1 = w1a[kq + 8], v1 = w1b[kq + 8], qa1 = xA[kq + 8], qb1 = xB[kq + 8];
        a0Al = fmaf(qa0.x, u0.x, a0Al); a0Al = fmaf(qa0.y, u0.y, a0Al);
        a0Al = fmaf(qa0.z, u0.z, a0Al); a0Al = fmaf(qa0.w, u0.w, a0Al);
        a0Ah = fmaf(qa1.x, u1.x, a0Ah); a0Ah = fmaf(qa1.y, u1.y, a0Ah);
        a0Ah = fmaf(qa1.z, u1.z, a0Ah); a0Ah = fmaf(qa1.w, u1.w, a0Ah);
        a1Al = fmaf(qa0.x, v0.x, a1Al); a1Al = fmaf(qa0.y, v0.y, a1Al);
        a1Al = fmaf(qa0.z, v0.z, a1Al); a1Al = fmaf(qa0.w, v0.w, a1Al);
        a1Ah = fmaf(qa1.x, v1.x, a1Ah); a1Ah = fmaf(qa1.y, v1.y, a1Ah);
        a1Ah = fmaf(qa1.z, v1.z, a1Ah); a1Ah = fmaf(qa1.w, v1.w, a1Ah);
        a0Bl = fmaf(qb0.x, u0.x, a0Bl); a0Bl = fmaf(qb0.y, u0.y, a0Bl);
        a0Bl = fmaf(qb0.z, u0.z, a0Bl); a0Bl = fmaf(qb0.w, u0.w, a0Bl);
        a0Bh = fmaf(qb1.x, u1.x, a0Bh); a0Bh = fmaf(qb1.y, u1.y, a0Bh);
        a0Bh = fmaf(qb1.z, u1.z, a0Bh); a0Bh = fmaf(qb1.w, u1.w, a0Bh);
        a1Bl = fmaf(qb0.x, v0.x, a1Bl); a1Bl = fmaf(qb0.y, v0.y, a1Bl);
        a1Bl = fmaf(qb0.z, v0.z, a1Bl); a1Bl = fmaf(qb0.w, v0.w, a1Bl);
        a1Bh = fmaf(qb1.x, v1.x, a1Bh); a1Bh = fmaf(qb1.y, v1.y, a1Bh);
        a1Bh = fmaf(qb1.z, v1.z, a1Bh); a1Bh = fmaf(qb1.w, v1.w, a1Bh);
    }
    float a0A = a0Al + a0Ah, a1A = a1Al + a1Ah;
    float a0B = a0Bl + a0Bh, a1B = a1Bl + a1Bh;
    a0A = (a0A > 0.0f) ? a0A : (ex2f(a0A * L2E) - 1.0f);   // ELU alpha=1
    a1A = (a1A > 0.0f) ? a1A : (ex2f(a1A * L2E) - 1.0f);
    a0B = (a0B > 0.0f) ? a0B : (ex2f(a0B * L2E) - 1.0f);
    a1B = (a1B > 0.0f) ? a1B : (ex2f(a1B * L2E) - 1.0f);
    sH[w][0][c0] = a0A; sH[w][0][c1] = a1A;
    sH[w][1][c0] = a0B; sH[w][1][c1] = a1B;
    __syncwarp();

    const float4* hA = reinterpret_cast<const float4*>(&sH[w][0][0]);
    const float4* hB = reinterpret_cast<const float4*>(&sH[w][1][0]);
    float z0Al = bib0, z0Ah = 0.f, z1Al = bib1, z1Ah = 0.f;
    float z0Bl = bib0, z0Bh = 0.f, z1Bl = bib1, z1Bh = 0.f;
#pragma unroll
    for (int kq = 0; kq < 8; kq++) {
        float4 u0 = w2a[kq], v0 = w2b[kq], qa0 = hA[kq], qb0 = hB[kq];
        float4 u1 = w2a[kq + 8], v1 = w2b[kq + 8], qa1 = hA[kq + 8], qb1 = hB[kq + 8];
        z0Al = fmaf(qa0.x, u0.x, z0Al); z0Al = fmaf(qa0.y, u0.y, z0Al);
        z0Al = fmaf(qa0.z, u0.z, z0Al); z0Al = fmaf(qa0.w, u0.w, z0Al);
        z0Ah = fmaf(qa1.x, u1.x, z0Ah); z0Ah = fmaf(qa1.y, u1.y, z0Ah);
        z0Ah = fmaf(qa1.z, u1.z, z0Ah); z0Ah = fmaf(qa1.w, u1.w, z0Ah);
        z1Al = fmaf(qa0.x, v0.x, z1Al); z1Al = fmaf(qa0.y, v0.y, z1Al);
        z1Al = fmaf(qa0.z, v0.z, z1Al); z1Al = fmaf(qa0.w, v0.w, z1Al);
        z1Ah = fmaf(qa1.x, v1.x, z1Ah); z1Ah = fmaf(qa1.y, v1.y, z1Ah);
        z1Ah = fmaf(qa1.z, v1.z, z1Ah); z1Ah = fmaf(qa1.w, v1.w, z1Ah);
        z0Bl = fmaf(qb0.x, u0.x, z0Bl); z0Bl = fmaf(qb0.y, u0.y, z0Bl);
        z0Bl = fmaf(qb0.z, u0.z, z0Bl); z0Bl = fmaf(qb0.w, u0.w, z0Bl);
        z0Bh = fmaf(qb1.x, u1.x, z0Bh); z0Bh = fmaf(qb1.y, u1.y, z0Bh);
        z0Bh = fmaf(qb1.z, u1.z, z0Bh); z0Bh = fmaf(qb1.w, u1.w, z0Bh);
        z1Bl = fmaf(qb0.x, v0.x, z1Bl); z1Bl = fmaf(qb0.y, v0.y, z1Bl);
        z1Bl = fmaf(qb0.z, v0.z, z1Bl); z1Bl = fmaf(qb0.w, v0.w, z1Bl);
        z1Bh = fmaf(qb1.x, v1.x, z1Bh); z1Bh = fmaf(qb1.y, v1.y, z1Bh);
        z1Bh = fmaf(qb1.z, v1.z, z1Bh); z1Bh = fmaf(qb1.w, v1.w, z1Bh);
    }
    float z0A = z0Al + z0Ah, z1A = z1Al + z1Ah;
    float z0B = z0Bl + z0Bh, z1B = z1Bl + z1Bh;
    float ssA = z0A * z0A + z1A * z1A;
    float ssB = z0B * z0B + z1B * z1B;
#pragma unroll
    for (int o = 16; o > 0; o >>= 1) {
        ssA += __shfl_xor_sync(0xffffffffu, ssA, o);
        ssB += __shfl_xor_sync(0xffffffffu, ssB, o);
    }
    float invA = 1.0f / fmaxf(sqrtf(ssA), 1e-12f);
    float invB = 1.0f / fmaxf(sqrtf(ssB), 1e-12f);
    out[rbase * 64 + c0]       = __float2half(z0A * invA);
    out[rbase * 64 + c1]       = __float2half(z1A * invA);
    out[(rbase + 1) * 64 + c0] = __float2half(z0B * invB);
    out[(rbase + 1) * 64 + c1] = __float2half(z1B * invB);
}

// ---------------- K2: single-MMA similarity (R11 structure, fp16 MMA) ----------------
#define SMEM_A    0
#define SMEM_B    16384
#define SMEM_COL  32768               // 8 warps x 128 floats = 4096 B
#define SMEM_CNT  36864               // 16 B (counter)
#define SMEM_Q    36880               // 512 x u32 = 2048 B
#define SMEM_RING 38928               // 8 warps x 4 stages x 512 B = 16384 B
#define SMEM_TOT  55312
#define QCAP 512

__global__ void __launch_bounds__(256, 4) sim_mma_kernel(const float* __restrict__ pos)
{
    extern __shared__ char smem[];
    uint32_t sbase = smem_u32(smem);
    float* sCol = reinterpret_cast<float*>(smem + SMEM_COL);
    int*   sCnt = reinterpret_cast<int*>(smem + SMEM_CNT);
    uint32_t* sQ = reinterpret_cast<uint32_t*>(smem + SMEM_Q);

    int tid = threadIdx.x, w = tid >> 5, lane = tid & 31;
    int bi = blockIdx.y, bj = blockIdx.x;

    if (tid == 0) *sCnt = 0;

    // ---- per-warp pos ring prologue: stages for nf = 0,1,2 (DRAM early)
    uint32_t ringw = sbase + SMEM_RING + w * 2048;            // 4 stages x 512B
    int prow = lane >> 1, phalf = lane & 1;
    const float* psrc = pos + (size_t)(bi * 128 + 16 * w + prow) * NN
                            + bj * 128 + phalf * 4;
    uint32_t pdst = ringw + prow * 32 + phalf * 16;
#pragma unroll
    for (int s = 0; s < 3; s++) {
        cp_async16(pdst + s * 512, psrc + s * 8);
        cp_commit();
    }

    // ---- load 2 fp16 tiles (SW128-swizzled): A=z1[bi], B=z2[bj]
    {
        const float4* srcA = reinterpret_cast<const float4*>(g_z1h) + bi * 1024;
        const float4* srcB = reinterpret_cast<const float4*>(g_z2h) + bj * 1024;
        for (int idx = tid; idx < 1024; idx += 256) {
            int rrow = idx >> 3, q = idx & 7;
            uint32_t sw = SWZ128((uint32_t)(rrow * 128 + q * 16));
            *reinterpret_cast<float4*>(smem + SMEM_A + sw) = srcA[idx];
            *reinterpret_cast<float4*>(smem + SMEM_B + sw) = srcB[idx];
        }
    }
    __syncthreads();

    // ---- A fragments (rows 16w..16w+15, K=64), loaded once
    int rr = lane & 7, g = lane >> 3;
    uint32_t a[16];
    {
        int rowA = 16 * w + (g & 1) * 8 + rr;
        int chA  = (g >> 1);
#pragma unroll
        for (int s = 0; s < 4; s++) {
            uint32_t off = SWZ128((uint32_t)(rowA * 128 + (2 * s + chA) * 16));
            ldsm_x4(a + 4 * s, sbase + SMEM_A + off);
        }
    }

    int qr = lane >> 2, qc = lane & 3;
    int R0 = bi * 128 + 16 * w + qr;
    int rloc0 = 16 * w + qr;
    int ringoff_w = SMEM_RING + w * 2048;

    float rs1a = 0.f, rs1b = 0.f, nm1a = 0.f, nm1b = 0.f;
    const float cexp = 1.8033688011f;              // log2(e)/tau

#pragma unroll
    for (int nf = 0; nf < 16; nf++) {
        if (nf <= 13)      asm volatile("cp.async.wait_group 2;" ::: "memory");
        else if (nf == 14) asm volatile("cp.async.wait_group 1;" ::: "memory");
        else               asm volatile("cp.async.wait_group 0;" ::: "memory");
        __syncwarp();

        int stage = nf & 3;
        const char* pstage = smem + ringoff_w + stage * 512;
        float2 p0 = *reinterpret_cast<const float2*>(pstage + qr * 32 + qc * 8);
        float2 p1 = *reinterpret_cast<const float2*>(pstage + qr * 32 + qc * 8 + 256);

        if (nf < 13) {
            cp_async16(ringw + ((nf + 3) & 3) * 512 + prow * 32 + phalf * 16,
                       psrc + (nf + 3) * 8);
            cp_commit();
        }

        uint32_t bb[8];
        int rowB = nf * 8 + rr;
        uint32_t offL = SWZ128((uint32_t)(rowB * 128 + g * 16));
        uint32_t offH = SWZ128((uint32_t)(rowB * 128 + (g + 4) * 16));
        ldsm_x4(bb,     sbase + SMEM_B + offL);
        ldsm_x4(bb + 4, sbase + SMEM_B + offH);

        uint32_t d[2] = {0u, 0u};                  // f16x2 accumulators (rows qr, qr+8)
#pragma unroll
        for (int s = 0; s < 4; s++) mma16816_f16(d, a + 4 * s, bb + 2 * s);

        float2 dl = __half22float2(reinterpret_cast<const __half2&>(d[0]));
        float2 dh = __half22float2(reinterpret_cast<const __half2&>(d[1]));
        float e0 = ex2f(dl.x * cexp), e1 = ex2f(dl.y * cexp);
        float e2 = ex2f(dh.x * cexp), e3 = ex2f(dh.y * cexp);

        rs1a += e0 + e1;  rs1b += e2 + e3;
        nm1a = fmaf(p0.x, e0, nm1a); nm1a = fmaf(p0.y, e1, nm1a);
        nm1b = fmaf(p1.x, e2, nm1b); nm1b = fmaf(p1.y, e3, nm1b);

        // colsum: reduce over qr, lanes 0..3 store once
        float c0v = e0 + e2, c1v = e1 + e3;
#pragma unroll
        for (int o = 4; o <= 16; o <<= 1) {
            c0v += __shfl_xor_sync(0xffffffffu, c0v, o);
            c1v += __shfl_xor_sync(0xffffffffu, c1v, o);
        }
        if (lane < 4) {
            sCol[w * 128 + nf * 8 + 2 * lane]     = c0v;
            sCol[w * 128 + nf * 8 + 2 * lane + 1] = c1v;
        }

        // sparse num2 queue, warp-ballot guarded
        bool nz = (p0.x != 0.0f) | (p0.y != 0.0f) | (p1.x != 0.0f) | (p1.y != 0.0f);
        if (__any_sync(0xffffffffu, nz)) {
            int cloc0 = nf * 8 + 2 * qc;
            if (p0.x != 0.0f) { int q_ = atomicAdd(sCnt, 1); if (q_ < QCAP) sQ[q_] = (uint32_t)((rloc0 << 8) | cloc0); }
            if (p0.y != 0.0f) { int q_ = atomicAdd(sCnt, 1); if (q_ < QCAP) sQ[q_] = (uint32_t)((rloc0 << 8) | (cloc0 + 1)); }
            if (p1.x != 0.0f) { int q_ = atomicAdd(sCnt, 1); if (q_ < QCAP) sQ[q_] = (uint32_t)(((rloc0 + 8) << 8) | cloc0); }
            if (p1.y != 0.0f) { int q_ = atomicAdd(sCnt, 1); if (q_ < QCAP) sQ[q_] = (uint32_t)(((rloc0 + 8) << 8) | (cloc0 + 1)); }
        }
    }

    // ---- rowsum/num1: quad reduce (over qc), leaders do atomics
#pragma unroll
    for (int o = 1; o <= 2; o <<= 1) {
        rs1a += __shfl_xor_sync(0xffffffffu, rs1a, o);
        rs1b += __shfl_xor_sync(0xffffffffu, rs1b, o);
        nm1a += __shfl_xor_sync(0xffffffffu, nm1a, o);
        nm1b += __shfl_xor_sync(0xffffffffu, nm1b, o);
    }
    if (qc == 0) {
        atomicAdd(&g_rowsum[R0],     rs1a);
        atomicAdd(&g_rowsum[R0 + 8], rs1b);
        atomicAdd(&g_num1[R0],       nm1a);
        atomicAdd(&g_num1[R0 + 8],   nm1b);
    }

    __syncthreads();

    // ---- colsum: reduce 8 warp slices
    if (tid < 128) {
        float s = 0.0f;
#pragma unroll
        for (int t = 0; t < 8; t++) s += sCol[t * 128 + tid];
        atomicAdd(&g_colsum[bj * 128 + tid], s);
    }

    // ---- sparse num2: one 64-dim fp16 dot per queued nonzero
    int cnt = *sCnt; if (cnt > QCAP) cnt = QCAP;
    for (int t = tid; t < cnt; t += 256) {
        uint32_t ent = sQ[t];
        int r_ = ent >> 8, c_ = ent & 255;
        int gr = bi * 128 + r_;
        int gc = bj * 128 + c_;
        const uint4* v1 = reinterpret_cast<const uint4*>(g_z1h + (size_t)gc * 64);
        const uint4* v2 = reinterpret_cast<const uint4*>(g_z2h + (size_t)gr * 64);
        float dot = 0.0f;
#pragma unroll
        for (int q_ = 0; q_ < 8; q_++) {
            uint4 u = v1[q_], v = v2[q_];
            dot = h2dot(u.x, v.x, dot);
            dot = h2dot(u.y, v.y, dot);
            dot = h2dot(u.z, v.z, dot);
            dot = h2dot(u.w, v.w, dot);
        }
        atomicAdd(&g_num2[gr], ex2f(dot * cexp));
    }
}

// ---------------- K3: final loss reduction ----------------
__global__ void __launch_bounds__(256) final_kernel(float* __restrict__ out)
{
    __shared__ float red[8];
    int i = blockIdx.x * 256 + threadIdx.x;
    float rsum = g_rowsum[i] + 1e-8f;
    float csum = g_colsum[i] + 1e-8f;
    float term = -0.5f * (logf(g_num1[i] / rsum + 1e-8f) +
                          logf(g_num2[i] / csum + 1e-8f)) * (1.0f / NN);
#pragma unroll
    for (int o = 16; o > 0; o >>= 1) term += __shfl_xor_sync(0xffffffffu, term, o);
    int w = threadIdx.x >> 5, lane = threadIdx.x & 31;
    if (lane == 0) red[w] = term;
    __syncthreads();
    if (threadIdx.x == 0) {
        float s = 0.0f;
#pragma unroll
        for (int t = 0; t < 8; t++) s += red[t];
        atomicAdd(out, s);
    }
}

// ---------------- host launcher ----------------
extern "C" void kernel_launch(void* const* d_in, const int* in_sizes, int n_in,
                              void* d_out, int out_size)
{
    const float* x1  = (const float*)d_in[0];
    const float* x2  = (const float*)d_in[1];
    const float* W1  = (const float*)d_in[2];
    const float* b1  = (const float*)d_in[3];
    const float* W2  = (const float*)d_in[4];
    const float* b2  = (const float*)d_in[5];
    const float* pos = (const float*)d_in[6];

    proj_kernel<<<1024, 256>>>(x1, x2, W1, b1, W2, b2, (float*)d_out);

    cudaFuncSetAttribute(sim_mma_kernel, cudaFuncAttributeMaxDynamicSharedMemorySize, SMEM_TOT);
    sim_mma_kernel<<<dim3(64, 64), 256, SMEM_TOT>>>(pos);

    final_kernel<<<32, 256>>>((float*)d_out);
}